// round 4
// baseline (speedup 1.0000x reference)
#include <cuda_runtime.h>
#include <cstdint>

#define ROWS 4096
#define COLS 8192
#define TPB  256
#define KK   8
// elements per thread = COLS / TPB = 32 = 8 float4

// Order-preserving float->uint map, packed with ~idx so that a single u64
// ">" gives (value desc, index asc) ordering.
__device__ __forceinline__ unsigned long long pack_key(float v, int idx) {
    unsigned u = __float_as_uint(v);
    unsigned fk = (u & 0x80000000u) ? ~u : (u | 0x80000000u);
    return ((unsigned long long)fk << 32) | (unsigned)(~(unsigned)idx);
}

__device__ __forceinline__ void unpack_key(unsigned long long k, float& v, int& idx) {
    unsigned fk = (unsigned)(k >> 32);
    unsigned u  = (fk & 0x80000000u) ? (fk ^ 0x80000000u) : ~fk;
    v   = __uint_as_float(u);
    idx = (int)(~(unsigned)(k & 0xFFFFFFFFull));
}

__device__ __forceinline__ void cmpswap(unsigned long long& a, unsigned long long& b) {
    unsigned long long lo = a < b ? a : b;
    a = a > b ? a : b;
    b = lo;
}

// Sort a bitonic 8-sequence into descending order (3-stage bitonic merge).
__device__ __forceinline__ void bitonic_clean8(unsigned long long (&k)[KK]) {
    cmpswap(k[0], k[4]); cmpswap(k[1], k[5]); cmpswap(k[2], k[6]); cmpswap(k[3], k[7]);
    cmpswap(k[0], k[2]); cmpswap(k[1], k[3]); cmpswap(k[4], k[6]); cmpswap(k[5], k[7]);
    cmpswap(k[0], k[1]); cmpswap(k[2], k[3]); cmpswap(k[4], k[5]); cmpswap(k[6], k[7]);
}

// Merge my descending-sorted 8-list with xor-partner's: result (identical on
// both lanes) is the descending-sorted top-8 of the union.
__device__ __forceinline__ void warp_merge_step(unsigned long long (&k)[KK], int d) {
    unsigned long long o[KK];
    #pragma unroll
    for (int i = 0; i < KK; i++)
        o[i] = __shfl_xor_sync(0xffffffffu, k[KK - 1 - i], d);  // partner reversed -> ascending
    #pragma unroll
    for (int i = 0; i < KK; i++)
        k[i] = k[i] > o[i] ? k[i] : o[i];   // top-8 of union, bitonic order
    bitonic_clean8(k);
}

// Insert candidate into descending-sorted 8-list (register resident).
__device__ __forceinline__ void insert8(unsigned long long (&k)[KK], unsigned long long c) {
    if (c > k[KK - 1]) {
        k[KK - 1] = c;
        #pragma unroll
        for (int j = KK - 1; j > 0; --j) {
            if (k[j] > k[j - 1]) { unsigned long long t = k[j]; k[j] = k[j - 1]; k[j - 1] = t; }
        }
    }
}

// IDX_MODE: 0 = indices as int64 at byte offset ROWS*KK*4
//           1 = indices as float32 at element offset ROWS*KK
template <int IDX_MODE>
__global__ __launch_bounds__(TPB) void topk8_kernel(const float* __restrict__ x,
                                                    void* __restrict__ d_out) {
    const int row = blockIdx.x;
    const int t   = threadIdx.x;
    const float4* xr = reinterpret_cast<const float4*>(x + (size_t)row * COLS);

    // Front-batched loads for MLP
    float4 v[8];
    #pragma unroll
    for (int i = 0; i < 8; i++)
        v[i] = xr[t + i * TPB];

    unsigned long long key[KK];
    #pragma unroll
    for (int i = 0; i < KK; i++) key[i] = 0ull;  // below any encoded real float

    #pragma unroll
    for (int i = 0; i < 8; i++) {
        int base = (t + i * TPB) * 4;
        insert8(key, pack_key(v[i].x, base + 0));
        insert8(key, pack_key(v[i].y, base + 1));
        insert8(key, pack_key(v[i].z, base + 2));
        insert8(key, pack_key(v[i].w, base + 3));
    }

    // Intra-warp merge: 32 lanes -> identical top-8 on every lane
    #pragma unroll
    for (int d = 1; d < 32; d <<= 1)
        warp_merge_step(key, d);

    // Cross-warp merge through shared memory
    __shared__ unsigned long long sm[TPB / 32][KK];
    const int warp = t >> 5, lane = t & 31;
    if (lane == 0) {
        #pragma unroll
        for (int i = 0; i < KK; i++) sm[warp][i] = key[i];
    }
    __syncthreads();

    if (warp == 0) {
        unsigned long long fk[KK];
        #pragma unroll
        for (int i = 0; i < KK; i++)
            fk[i] = (lane < TPB / 32) ? sm[lane][i] : 0ull;
        warp_merge_step(fk, 1);
        warp_merge_step(fk, 2);
        warp_merge_step(fk, 4);

        if (lane == 0) {
            float* out_v = (float*)d_out;
            #pragma unroll
            for (int i = 0; i < KK; i++) {
                float val; int idx;
                unpack_key(fk[i], val, idx);
                out_v[(size_t)row * KK + i] = val;
                if (IDX_MODE == 1) {
                    // whole buffer is float32; indices stored as float casts
                    float* out_i = out_v + (size_t)ROWS * KK;
                    out_i[(size_t)row * KK + i] = (float)idx;
                } else {
                    // indices stored as int64 after the float32 values block
                    long long* out_i = (long long*)((char*)d_out + (size_t)ROWS * KK * sizeof(float));
                    out_i[(size_t)row * KK + i] = (long long)idx;
                }
            }
        }
    }
}

extern "C" void kernel_launch(void* const* d_in, const int* in_sizes, int n_in,
                              void* d_out, int out_size) {
    const float* x = (const float*)d_in[0];
    // Distinguish output layout by total element count:
    //   values(32768 f32) + indices(32768 f32/int32)  -> out_size == 65536
    //   values(32768 f32) + indices(32768 int64)      -> out_size != 65536 (e.g. 98304)
    if (out_size == 2 * ROWS * KK) {
        topk8_kernel<1><<<ROWS, TPB>>>(x, d_out);
    } else {
        topk8_kernel<0><<<ROWS, TPB>>>(x, d_out);
    }
}

// round 7
// speedup vs baseline: 4.0104x; 4.0104x over previous
#include <cuda_runtime.h>
#include <cstdint>

#define ROWS 4096
#define COLS 8192
#define TPB  256
#define KK   8
#define TH   2.75f
#define SCAP 1024

// ---------- packed key helpers ----------

// Order-preserving float->uint map, packed with ~idx so that a single u64
// ">" gives (value desc, index asc) ordering.
__device__ __forceinline__ unsigned long long pack_key(float v, int idx) {
    unsigned u = __float_as_uint(v);
    unsigned fk = (u & 0x80000000u) ? ~u : (u | 0x80000000u);
    return ((unsigned long long)fk << 32) | (unsigned)(~(unsigned)idx);
}

__device__ __forceinline__ void unpack_key(unsigned long long k, float& v, int& idx) {
    unsigned fk = (unsigned)(k >> 32);
    unsigned u  = (fk & 0x80000000u) ? (fk ^ 0x80000000u) : ~fk;
    v   = __uint_as_float(u);
    idx = (int)(~(unsigned)(k & 0xFFFFFFFFull));
}

// ---------- exact top-8 machinery (proven in R4) ----------

__device__ __forceinline__ void cmpswap(unsigned long long& a, unsigned long long& b) {
    unsigned long long lo = a < b ? a : b;
    a = a > b ? a : b;
    b = lo;
}

__device__ __forceinline__ void bitonic_clean8(unsigned long long (&k)[KK]) {
    cmpswap(k[0], k[4]); cmpswap(k[1], k[5]); cmpswap(k[2], k[6]); cmpswap(k[3], k[7]);
    cmpswap(k[0], k[2]); cmpswap(k[1], k[3]); cmpswap(k[4], k[6]); cmpswap(k[5], k[7]);
    cmpswap(k[0], k[1]); cmpswap(k[2], k[3]); cmpswap(k[4], k[5]); cmpswap(k[6], k[7]);
}

__device__ __forceinline__ void warp_merge_step(unsigned long long (&k)[KK], int d) {
    unsigned long long o[KK];
    #pragma unroll
    for (int i = 0; i < KK; i++)
        o[i] = __shfl_xor_sync(0xffffffffu, k[KK - 1 - i], d);
    #pragma unroll
    for (int i = 0; i < KK; i++)
        k[i] = k[i] > o[i] ? k[i] : o[i];
    bitonic_clean8(k);
}

__device__ __forceinline__ void insert8(unsigned long long (&k)[KK], unsigned long long c) {
    if (c > k[KK - 1]) {
        k[KK - 1] = c;
        #pragma unroll
        for (int j = KK - 1; j > 0; --j) {
            if (k[j] > k[j - 1]) { unsigned long long t = k[j]; k[j] = k[j - 1]; k[j - 1] = t; }
        }
    }
}

// IDX_MODE: 1 = indices as float32 at element offset ROWS*KK (confirmed layout)
//           0 = indices as int64 at byte offset ROWS*KK*4 (fallback)
template <int IDX_MODE>
__device__ __forceinline__ void write_row_out(void* d_out, int row,
                                              const unsigned long long (&k)[KK]) {
    float* out_v = (float*)d_out;
    #pragma unroll
    for (int i = 0; i < KK; i++) {
        float val; int idx;
        unpack_key(k[i], val, idx);
        out_v[(size_t)row * KK + i] = val;
        if (IDX_MODE == 1) {
            float* out_i = out_v + (size_t)ROWS * KK;
            out_i[(size_t)row * KK + i] = (float)idx;
        } else {
            long long* out_i = (long long*)((char*)d_out + (size_t)ROWS * KK * sizeof(float));
            out_i[(size_t)row * KK + i] = (long long)idx;
        }
    }
}

// ---------- kernel ----------

template <int IDX_MODE>
__global__ __launch_bounds__(TPB) void topk8_kernel(const float* __restrict__ x,
                                                    void* __restrict__ d_out) {
    const int row  = blockIdx.x;
    const int t    = threadIdx.x;
    const int wid  = t >> 5;
    const int lane = t & 31;

    __shared__ int s_tid[TPB];
    __shared__ unsigned long long s_cand[SCAP];
    __shared__ int s_nhit, s_ncand;
    __shared__ unsigned long long s_top[TPB / 32][KK];

    if (t == 0) { s_nhit = 0; s_ncand = 0; }

    // ---- Phase 1: branchless scalar fmax tree over this thread's 32 elems ----
    const float4* xr = reinterpret_cast<const float4*>(x + (size_t)row * COLS);
    float4 v[8];
    #pragma unroll
    for (int i = 0; i < 8; i++)
        v[i] = xr[t + i * TPB];

    float m[8];
    #pragma unroll
    for (int i = 0; i < 8; i++)
        m[i] = fmaxf(fmaxf(v[i].x, v[i].y), fmaxf(v[i].z, v[i].w));
    m[0] = fmaxf(m[0], m[1]); m[2] = fmaxf(m[2], m[3]);
    m[4] = fmaxf(m[4], m[5]); m[6] = fmaxf(m[6], m[7]);
    m[0] = fmaxf(m[0], m[2]); m[4] = fmaxf(m[4], m[6]);
    float mx = fmaxf(m[0], m[4]);

    __syncthreads();  // s_nhit/s_ncand init visible

    if (mx > TH) {
        int p = atomicAdd(&s_nhit, 1);
        s_tid[p] = t;  // p < TPB always
    }
    __syncthreads();

    // ---- Phase 2: cooperative restage of hit blocks, compact candidates ----
    const int nhit = s_nhit;
    for (int j = wid; j < nhit; j += TPB / 32) {
        int ht   = s_tid[j];
        int f4   = lane >> 2;
        int comp = lane & 3;
        int gidx = (ht + f4 * TPB) * 4 + comp;   // 32 lanes cover hit-thread's 32 elems
        float f = x[(size_t)row * COLS + gidx];
        if (f > TH) {
            int p = atomicAdd(&s_ncand, 1);
            if (p < SCAP) s_cand[p] = pack_key(f, gidx);
        }
    }
    __syncthreads();

    const int ncand = s_ncand;

    if (ncand >= KK && ncand <= SCAP) {
        // ---- Phase 3 (common): exact top-8 of small candidate set, warp 0 only ----
        if (wid == 0) {
            unsigned long long key[KK];
            #pragma unroll
            for (int i = 0; i < KK; i++) key[i] = 0ull;
            for (int j = lane; j < ncand; j += 32)
                insert8(key, s_cand[j]);
            #pragma unroll
            for (int d = 1; d < 32; d <<= 1)
                warp_merge_step(key, d);
            if (lane == 0)
                write_row_out<IDX_MODE>(d_out, row, key);
        }
    } else {
        // ---- Fallback (rare, any-input-correct): full exact scan (R4 algorithm) ----
        unsigned long long key[KK];
        #pragma unroll
        for (int i = 0; i < KK; i++) key[i] = 0ull;
        #pragma unroll
        for (int i = 0; i < 8; i++) {
            int base = (t + i * TPB) * 4;
            insert8(key, pack_key(v[i].x, base + 0));
            insert8(key, pack_key(v[i].y, base + 1));
            insert8(key, pack_key(v[i].z, base + 2));
            insert8(key, pack_key(v[i].w, base + 3));
        }
        #pragma unroll
        for (int d = 1; d < 32; d <<= 1)
            warp_merge_step(key, d);
        if (lane == 0) {
            #pragma unroll
            for (int i = 0; i < KK; i++) s_top[wid][i] = key[i];
        }
        __syncthreads();  // uniform branch: whole CTA takes this path together
        if (wid == 0) {
            unsigned long long fk[KK];
            #pragma unroll
            for (int i = 0; i < KK; i++)
                fk[i] = (lane < TPB / 32) ? s_top[lane][i] : 0ull;
            warp_merge_step(fk, 1);
            warp_merge_step(fk, 2);
            warp_merge_step(fk, 4);
            if (lane == 0)
                write_row_out<IDX_MODE>(d_out, row, fk);
        }
    }
}

extern "C" void kernel_launch(void* const* d_in, const int* in_sizes, int n_in,
                              void* d_out, int out_size) {
    const float* x = (const float*)d_in[0];
    if (out_size == 2 * ROWS * KK) {
        topk8_kernel<1><<<ROWS, TPB>>>(x, d_out);
    } else {
        topk8_kernel<0><<<ROWS, TPB>>>(x, d_out);
    }
}

// round 11
// speedup vs baseline: 4.0760x; 1.0163x over previous
#include <cuda_runtime.h>
#include <cstdint>

#define ROWS 4096
#define COLS 8192
#define TPB  512
#define EPT  16            // elements per thread = COLS / TPB
#define NW   (TPB / 32)    // 16 warps
#define KK   8
#define TH   2.75f
#define SCAP 1024

// ---------- packed key helpers ----------

// Order-preserving float->uint map, packed with ~idx so that a single u64
// ">" gives (value desc, index asc) ordering.
__device__ __forceinline__ unsigned long long pack_key(float v, int idx) {
    unsigned u = __float_as_uint(v);
    unsigned fk = (u & 0x80000000u) ? ~u : (u | 0x80000000u);
    return ((unsigned long long)fk << 32) | (unsigned)(~(unsigned)idx);
}

__device__ __forceinline__ void unpack_key(unsigned long long k, float& v, int& idx) {
    unsigned fk = (unsigned)(k >> 32);
    unsigned u  = (fk & 0x80000000u) ? (fk ^ 0x80000000u) : ~fk;
    v   = __uint_as_float(u);
    idx = (int)(~(unsigned)(k & 0xFFFFFFFFull));
}

// ---------- exact top-8 machinery (proven) ----------

__device__ __forceinline__ void cmpswap(unsigned long long& a, unsigned long long& b) {
    unsigned long long lo = a < b ? a : b;
    a = a > b ? a : b;
    b = lo;
}

__device__ __forceinline__ void bitonic_clean8(unsigned long long (&k)[KK]) {
    cmpswap(k[0], k[4]); cmpswap(k[1], k[5]); cmpswap(k[2], k[6]); cmpswap(k[3], k[7]);
    cmpswap(k[0], k[2]); cmpswap(k[1], k[3]); cmpswap(k[4], k[6]); cmpswap(k[5], k[7]);
    cmpswap(k[0], k[1]); cmpswap(k[2], k[3]); cmpswap(k[4], k[5]); cmpswap(k[6], k[7]);
}

__device__ __forceinline__ void warp_merge_step(unsigned long long (&k)[KK], int d) {
    unsigned long long o[KK];
    #pragma unroll
    for (int i = 0; i < KK; i++)
        o[i] = __shfl_xor_sync(0xffffffffu, k[KK - 1 - i], d);
    #pragma unroll
    for (int i = 0; i < KK; i++)
        k[i] = k[i] > o[i] ? k[i] : o[i];
    bitonic_clean8(k);
}

__device__ __forceinline__ void insert8(unsigned long long (&k)[KK], unsigned long long c) {
    if (c > k[KK - 1]) {
        k[KK - 1] = c;
        #pragma unroll
        for (int j = KK - 1; j > 0; --j) {
            if (k[j] > k[j - 1]) { unsigned long long t = k[j]; k[j] = k[j - 1]; k[j - 1] = t; }
        }
    }
}

// IDX_MODE: 1 = indices as float32 at element offset ROWS*KK (confirmed layout)
//           0 = indices as int64 at byte offset ROWS*KK*4 (fallback)
template <int IDX_MODE>
__device__ __forceinline__ void write_row_out(void* d_out, int row,
                                              const unsigned long long (&k)[KK]) {
    float* out_v = (float*)d_out;
    #pragma unroll
    for (int i = 0; i < KK; i++) {
        float val; int idx;
        unpack_key(k[i], val, idx);
        out_v[(size_t)row * KK + i] = val;
        if (IDX_MODE == 1) {
            float* out_i = out_v + (size_t)ROWS * KK;
            out_i[(size_t)row * KK + i] = (float)idx;
        } else {
            long long* out_i = (long long*)((char*)d_out + (size_t)ROWS * KK * sizeof(float));
            out_i[(size_t)row * KK + i] = (long long)idx;
        }
    }
}

// ---------- kernel ----------

template <int IDX_MODE>
__global__ __launch_bounds__(TPB, 3) void topk8_kernel(const float* __restrict__ x,
                                                       void* __restrict__ d_out) {
    const int row  = blockIdx.x;
    const int t    = threadIdx.x;
    const int wid  = t >> 5;
    const int lane = t & 31;

    __shared__ unsigned long long s_cand[SCAP];
    __shared__ int s_ncand;
    __shared__ unsigned long long s_top[NW][KK];

    if (t == 0) s_ncand = 0;

    // ---- Phase 1: load 16 elems (4 x float4), branchless fmax tree ----
    const float4* xr = reinterpret_cast<const float4*>(x + (size_t)row * COLS);
    float4 v[4];
    #pragma unroll
    for (int i = 0; i < 4; i++)
        v[i] = xr[t + i * TPB];

    float m[4];
    #pragma unroll
    for (int i = 0; i < 4; i++)
        m[i] = fmaxf(fmaxf(v[i].x, v[i].y), fmaxf(v[i].z, v[i].w));
    float mx = fmaxf(fmaxf(m[0], m[1]), fmaxf(m[2], m[3]));

    __syncthreads();  // s_ncand init visible

    // ---- Phase 2: register-direct candidate extraction (no global re-read) ----
    if (mx > TH) {
        #pragma unroll
        for (int i = 0; i < 4; i++) {
            int base = (t + i * TPB) * 4;
            float f;
            f = v[i].x; if (f > TH) { int p = atomicAdd(&s_ncand, 1); if (p < SCAP) s_cand[p] = pack_key(f, base + 0); }
            f = v[i].y; if (f > TH) { int p = atomicAdd(&s_ncand, 1); if (p < SCAP) s_cand[p] = pack_key(f, base + 1); }
            f = v[i].z; if (f > TH) { int p = atomicAdd(&s_ncand, 1); if (p < SCAP) s_cand[p] = pack_key(f, base + 2); }
            f = v[i].w; if (f > TH) { int p = atomicAdd(&s_ncand, 1); if (p < SCAP) s_cand[p] = pack_key(f, base + 3); }
        }
    }
    __syncthreads();

    const int ncand = s_ncand;

    if (ncand >= KK && ncand <= SCAP) {
        // ---- Phase 3 (common): exact top-8 of ~24 candidates, warp 0 only ----
        if (wid == 0) {
            unsigned long long key[KK];
            #pragma unroll
            for (int i = 0; i < KK; i++) key[i] = 0ull;
            for (int j = lane; j < ncand; j += 32)
                insert8(key, s_cand[j]);
            #pragma unroll
            for (int d = 1; d < 32; d <<= 1)
                warp_merge_step(key, d);
            if (lane == 0)
                write_row_out<IDX_MODE>(d_out, row, key);
        }
    } else {
        // ---- Fallback (rare, any-input-correct): full exact scan ----
        unsigned long long key[KK];
        #pragma unroll
        for (int i = 0; i < KK; i++) key[i] = 0ull;
        #pragma unroll
        for (int i = 0; i < 4; i++) {
            int base = (t + i * TPB) * 4;
            insert8(key, pack_key(v[i].x, base + 0));
            insert8(key, pack_key(v[i].y, base + 1));
            insert8(key, pack_key(v[i].z, base + 2));
            insert8(key, pack_key(v[i].w, base + 3));
        }
        #pragma unroll
        for (int d = 1; d < 32; d <<= 1)
            warp_merge_step(key, d);
        if (lane == 0) {
            #pragma unroll
            for (int i = 0; i < KK; i++) s_top[wid][i] = key[i];
        }
        __syncthreads();  // uniform branch: whole CTA takes this path together
        if (wid == 0) {
            unsigned long long fk[KK];
            #pragma unroll
            for (int i = 0; i < KK; i++)
                fk[i] = (lane < NW) ? s_top[lane][i] : 0ull;
            warp_merge_step(fk, 1);
            warp_merge_step(fk, 2);
            warp_merge_step(fk, 4);
            warp_merge_step(fk, 8);
            if (lane == 0)
                write_row_out<IDX_MODE>(d_out, row, fk);
        }
    }
}

extern "C" void kernel_launch(void* const* d_in, const int* in_sizes, int n_in,
                              void* d_out, int out_size) {
    const float* x = (const float*)d_in[0];
    if (out_size == 2 * ROWS * KK) {
        topk8_kernel<1><<<ROWS, TPB>>>(x, d_out);
    } else {
        topk8_kernel<0><<<ROWS, TPB>>>(x, d_out);
    }
}